// round 7
// baseline (speedup 1.0000x reference)
#include <cuda_runtime.h>
#include <cuda_bf16.h>

#define B_ 4
#define N_ 512
#define D_ 128
#define H_ 128

typedef unsigned long long ull;

// ---- packed f32x2 helpers -------------------------------------------------
__device__ __forceinline__ void fma2(ull &a, ull x, ull w) {
    asm("fma.rn.f32x2 %0, %1, %2, %0;" : "+l"(a) : "l"(x), "l"(w));
}
__device__ __forceinline__ ull add2(ull a, ull b) {
    ull r; asm("add.rn.f32x2 %0, %1, %2;" : "=l"(r) : "l"(a), "l"(b)); return r;
}
__device__ __forceinline__ ull pack2(float lo, float hi) {
    ull r; asm("mov.b64 %0, {%1, %2};" : "=l"(r) : "f"(lo), "f"(hi)); return r;
}
__device__ __forceinline__ void unpack2(ull v, float &lo, float &hi) {
    asm("mov.b64 {%0, %1}, %2;" : "=f"(lo), "=f"(hi) : "l"(v));
}
__device__ __forceinline__ float hadd2(ull v) { float lo, hi; unpack2(v, lo, hi); return lo + hi; }
__device__ __forceinline__ ull relu2(ull v) {
    float lo, hi; unpack2(v, lo, hi);
    return pack2(fmaxf(lo, 0.f), fmaxf(hi, 0.f));
}

// ---- scratch --------------------------------------------------------------
__device__ float gA[B_ * N_ * H_];
__device__ float gC[B_ * N_ * H_];
__device__ float gDiag[B_ * N_];

// ---------------------------------------------------------------------------
// Precompute v7: 16 rows/block, grid 128, 256 threads = h(128) x d-half(2).
// f32x2 packs ROW PAIRS (weights broadcast-packed); X transposed in smem so
// each row-pair load is one broadcast LDS.64. Distance-2 W register prefetch.
// ---------------------------------------------------------------------------
#define RWP 16

__global__ __launch_bounds__(256) void precompute_kernel(
    const float* __restrict__ X,
    const float* __restrict__ W1c, const float* __restrict__ b1c,
    const float* __restrict__ W1s, const float* __restrict__ b1s,
    const float* __restrict__ W2s, const float* __restrict__ b2s)
{
    const int tid  = threadIdx.x;
    const int h    = tid & 127;
    const int half = tid >> 7;
    const int blockRow = blockIdx.x * RWP;

    __shared__ float xsT[D_][18];          // transposed X, padded (9.2 KB)
    __shared__ ull   red[128][25];         // half-1 partials     (25.6 KB)
    __shared__ float red4[4][RWP];

    // load X rows, store transposed
    for (int k = tid; k < RWP * D_; k += 256) {
        const int r = k >> 7;              // 0..15
        const int d = k & 127;
        xsT[d][r] = X[(size_t)blockRow * D_ + k];
    }
    __syncthreads();

    ull accA[8], accC[8], accS[8];
#pragma unroll
    for (int rp = 0; rp < 8; rp++) { accA[rp] = 0ull; accC[rp] = 0ull; accS[rp] = 0ull; }

    const int dBase = half * 64;
    const float* pA = W1c + (size_t)dBase * H_ + h;
    const float* pC = W1c + (size_t)(dBase + D_) * H_ + h;
    const float* pS = W1s + (size_t)dBase * H_ + h;

    float wb[3][6];
#pragma unroll
    for (int p = 0; p < 2; p++)
#pragma unroll
        for (int e = 0; e < 2; e++) {
            wb[p][e]     = pA[(size_t)(2 * p + e) * H_];
            wb[p][2 + e] = pC[(size_t)(2 * p + e) * H_];
            wb[p][4 + e] = pS[(size_t)(2 * p + e) * H_];
        }

#pragma unroll
    for (int s = 0; s < 32; s++) {         // 32 steps x 2 d = 64 d per half
        const int cur = s % 3;
        if (s < 30) {
            const int nb  = (s + 2) % 3;
            const int off = (s + 2) * 2;
#pragma unroll
            for (int e = 0; e < 2; e++) {
                wb[nb][e]     = pA[(size_t)(off + e) * H_];
                wb[nb][2 + e] = pC[(size_t)(off + e) * H_];
                wb[nb][4 + e] = pS[(size_t)(off + e) * H_];
            }
        }
#pragma unroll
        for (int e = 0; e < 2; e++) {
            const int d = dBase + s * 2 + e;
            const ull wa2 = pack2(wb[cur][e],     wb[cur][e]);
            const ull wc2 = pack2(wb[cur][2 + e], wb[cur][2 + e]);
            const ull ws2 = pack2(wb[cur][4 + e], wb[cur][4 + e]);
#pragma unroll
            for (int rp = 0; rp < 8; rp++) {
                const ull xv = *(const ull*)&xsT[d][rp * 2];   // broadcast
                fma2(accA[rp], xv, wa2);
                fma2(accC[rp], xv, wc2);
                fma2(accS[rp], xv, ws2);
            }
        }
    }

    if (half) {
#pragma unroll
        for (int rp = 0; rp < 8; rp++) {
            red[h][rp]      = accA[rp];
            red[h][8 + rp]  = accC[rp];
            red[h][16 + rp] = accS[rp];
        }
    }
    __syncthreads();

    if (!half) {
        const float bc = b1c[h];
        const float bs = b1s[h];
        const float w2 = W2s[h];
        const int warp = tid >> 5;
#pragma unroll
        for (int rp = 0; rp < 8; rp++) {
            float a0, a1, c0, c1, s0, s1;
            unpack2(add2(accA[rp], red[h][rp]),      a0, a1);
            unpack2(add2(accC[rp], red[h][8 + rp]),  c0, c1);
            unpack2(add2(accS[rp], red[h][16 + rp]), s0, s1);
            const size_t r0 = (size_t)(blockRow + 2 * rp) * H_ + h;
            gA[r0]      = a0;
            gA[r0 + H_] = a1;
            gC[r0]      = c0 + bc;
            gC[r0 + H_] = c1 + bc;
            float t0 = fmaxf(s0 + bs, 0.f) * w2;
            float t1 = fmaxf(s1 + bs, 0.f) * w2;
#pragma unroll
            for (int off = 16; off > 0; off >>= 1) {
                t0 += __shfl_down_sync(0xffffffffu, t0, off);
                t1 += __shfl_down_sync(0xffffffffu, t1, off);
            }
            if ((tid & 31) == 0) {
                red4[warp][2 * rp]     = t0;
                red4[warp][2 * rp + 1] = t1;
            }
        }
    }
    __syncthreads();
    if (tid < RWP) {
        const float s = red4[0][tid] + red4[1][tid] + red4[2][tid] + red4[3][tid] + b2s[0];
        gDiag[blockRow + tid] = 1.f / (1.f + __expf(-s));
    }
}

// ---------------------------------------------------------------------------
// Pair kernel v7: 16x16 tile, 64 threads, 2x2 micro over full h=128.
// Exact triangular grid (528 tiles/batch), 12-blocks/SM residency hint.
// ---------------------------------------------------------------------------
__global__ __launch_bounds__(64, 12) void pair_kernel(
    const float* __restrict__ W2c, const float* __restrict__ b2c,
    float* __restrict__ out)
{
    int t = blockIdx.x, ti = 0;
    while (t >= 32 - ti) { t -= 32 - ti; ti++; }
    const int tj = ti + t;
    const int b  = blockIdx.y;

    __shared__ float As[16][132];
    __shared__ float Cs[16][132];
    __shared__ float St[16][17];
    __shared__ float ws[H_];

    const int tid = threadIdx.x;
    const int i0 = ti * 16, j0 = tj * 16;

    {
        const float4* ga4 = (const float4*)(gA + ((size_t)b * N_ + i0) * H_);
        const float4* gc4 = (const float4*)(gC + ((size_t)b * N_ + j0) * H_);
#pragma unroll
        for (int k = 0; k < 8; k++) {
            const int e = k * 64 + tid;
            const int r = e >> 5, c = e & 31;
            ((float4*)&As[r][0])[c] = ga4[r * 32 + c];
            ((float4*)&Cs[r][0])[c] = gc4[r * 32 + c];
        }
        ws[tid] = W2c[tid];
        ws[tid + 64] = W2c[tid + 64];
    }
    __syncthreads();

    const int ty = tid >> 3;
    const int tx = tid & 7;

    ull a00 = 0ull, a01 = 0ull, a10 = 0ull, a11 = 0ull;

#pragma unroll 8
    for (int hh = 0; hh < H_; hh += 4) {
        const ulonglong2 av0 = *(const ulonglong2*)&As[ty][hh];
        const ulonglong2 av1 = *(const ulonglong2*)&As[ty + 8][hh];
        const ulonglong2 cv0 = *(const ulonglong2*)&Cs[tx][hh];
        const ulonglong2 cv1 = *(const ulonglong2*)&Cs[tx + 8][hh];
        const ulonglong2 wv  = *(const ulonglong2*)&ws[hh];

        fma2(a00, relu2(add2(av0.x, cv0.x)), wv.x);
        fma2(a00, relu2(add2(av0.y, cv0.y)), wv.y);
        fma2(a01, relu2(add2(av0.x, cv1.x)), wv.x);
        fma2(a01, relu2(add2(av0.y, cv1.y)), wv.y);
        fma2(a10, relu2(add2(av1.x, cv0.x)), wv.x);
        fma2(a10, relu2(add2(av1.y, cv0.y)), wv.y);
        fma2(a11, relu2(add2(av1.x, cv1.x)), wv.x);
        fma2(a11, relu2(add2(av1.y, cv1.y)), wv.y);
    }

    const float bb = b2c[0];
    const float s00 = 1.f / (1.f + __expf(-(hadd2(a00) + bb)));
    const float s01 = 1.f / (1.f + __expf(-(hadd2(a01) + bb)));
    const float s10 = 1.f / (1.f + __expf(-(hadd2(a10) + bb)));
    const float s11 = 1.f / (1.f + __expf(-(hadd2(a11) + bb)));

    if (ti != tj) {
        St[ty][tx]         = s00;
        St[ty][tx + 8]     = s01;
        St[ty + 8][tx]     = s10;
        St[ty + 8][tx + 8] = s11;
        __syncthreads();

        const int r = tid >> 2, c = (tid & 3) * 4;
        float4 v = make_float4(St[r][c], St[r][c + 1], St[r][c + 2], St[r][c + 3]);
        *(float4*)&out[((size_t)b * N_ + i0 + r) * N_ + j0 + c] = v;
        float4 vt = make_float4(St[c][r], St[c + 1][r], St[c + 2][r], St[c + 3][r]);
        *(float4*)&out[((size_t)b * N_ + j0 + r) * N_ + i0 + c] = vt;
    } else {
        const int gi0 = b * N_ + i0;
        const float sv[2][2] = {{s00, s01}, {s10, s11}};
#pragma unroll
        for (int k = 0; k < 2; k++) {
#pragma unroll
            for (int m = 0; m < 2; m++) {
                const int i = ty + 8 * k, j = tx + 8 * m;
                if (i < j)       { St[i][j] = sv[k][m]; St[j][i] = sv[k][m]; }
                else if (i == j) { St[i][i] = gDiag[gi0 + i]; }
            }
        }
        __syncthreads();
        const int r = tid >> 2, c = (tid & 3) * 4;
        float4 v = make_float4(St[r][c], St[r][c + 1], St[r][c + 2], St[r][c + 3]);
        *(float4*)&out[((size_t)b * N_ + i0 + r) * N_ + j0 + c] = v;
    }
}

// ---------------------------------------------------------------------------
extern "C" void kernel_launch(void* const* d_in, const int* in_sizes, int n_in,
                              void* d_out, int out_size)
{
    const float* X   = (const float*)d_in[0];
    const float* W1c = (const float*)d_in[1];
    const float* b1c = (const float*)d_in[2];
    const float* W2c = (const float*)d_in[3];
    const float* b2c = (const float*)d_in[4];
    const float* W1s = (const float*)d_in[5];
    const float* b1s = (const float*)d_in[6];
    const float* W2s = (const float*)d_in[7];
    const float* b2s = (const float*)d_in[8];
    float* out = (float*)d_out;

    precompute_kernel<<<(B_ * N_) / RWP, 256>>>(X, W1c, b1c, W1s, b1s, W2s, b2s);

    dim3 grid(528, B_);   // exact upper-triangular 16x16 tiles x batch
    pair_kernel<<<grid, 64>>>(W2c, b2c, out);
}

// round 8
// speedup vs baseline: 1.5804x; 1.5804x over previous
#include <cuda_runtime.h>
#include <cuda_bf16.h>

#define B_ 4
#define N_ 512
#define D_ 128
#define H_ 128

typedef unsigned long long ull;

// ---- packed f32x2 helpers -------------------------------------------------
__device__ __forceinline__ void fma2(ull &a, ull x, ull w) {
    asm("fma.rn.f32x2 %0, %1, %2, %0;" : "+l"(a) : "l"(x), "l"(w));
}
__device__ __forceinline__ ull add2(ull a, ull b) {
    ull r; asm("add.rn.f32x2 %0, %1, %2;" : "=l"(r) : "l"(a), "l"(b)); return r;
}
__device__ __forceinline__ ull pack2(float lo, float hi) {
    ull r; asm("mov.b64 %0, {%1, %2};" : "=l"(r) : "f"(lo), "f"(hi)); return r;
}
__device__ __forceinline__ void unpack2(ull v, float &lo, float &hi) {
    asm("mov.b64 {%0, %1}, %2;" : "=f"(lo), "=f"(hi) : "l"(v));
}
__device__ __forceinline__ float hadd2(ull v) { float lo, hi; unpack2(v, lo, hi); return lo + hi; }
__device__ __forceinline__ ull relu2(ull v) {
    float lo, hi; unpack2(v, lo, hi);
    return pack2(fmaxf(lo, 0.f), fmaxf(hi, 0.f));
}

// ---- scratch --------------------------------------------------------------
__device__ float gA[B_ * N_ * H_];
__device__ float gC[B_ * N_ * H_];
__device__ float gDiag[B_ * N_];

// ---------------------------------------------------------------------------
// Precompute (round-4 version, measured ~7.9us): 8 rows/block, 256 threads =
// h(128) x d-half(2), grid 256. Distance-2 weight prefetch (3 buffers).
// ---------------------------------------------------------------------------
#define RW 8

__global__ __launch_bounds__(256) void precompute_kernel(
    const float* __restrict__ X,
    const float* __restrict__ W1c, const float* __restrict__ b1c,
    const float* __restrict__ W1s, const float* __restrict__ b1s,
    const float* __restrict__ W2s, const float* __restrict__ b2s)
{
    const int tid  = threadIdx.x;
    const int h    = tid & 127;
    const int half = tid >> 7;
    const int rowBase = blockIdx.x * RW;

    __shared__ float xs[RW][D_];
    __shared__ float redA[RW][H_];
    __shared__ float redC[RW][H_];
    __shared__ float redS[RW][H_];
    __shared__ float red4[4][RW];

    {
        const float4* src = (const float4*)(X + (size_t)rowBase * D_);
        float4* dst = (float4*)&xs[0][0];
        for (int t = tid; t < RW * D_ / 4; t += 256) dst[t] = src[t];
    }
    __syncthreads();

    ull accA[RW], accC[RW], accS[RW];
#pragma unroll
    for (int r = 0; r < RW; r++) { accA[r] = 0ull; accC[r] = 0ull; accS[r] = 0ull; }

    const int dBase = half * 64;
    const float* pA = W1c + (size_t)dBase * H_ + h;
    const float* pC = W1c + (size_t)(dBase + D_) * H_ + h;
    const float* pS = W1s + (size_t)dBase * H_ + h;

    float wb[3][12];
#pragma unroll
    for (int p = 0; p < 2; p++) {
#pragma unroll
        for (int q = 0; q < 4; q++) {
            wb[p][q]     = pA[(p * 4 + q) * H_];
            wb[p][4 + q] = pC[(p * 4 + q) * H_];
            wb[p][8 + q] = pS[(p * 4 + q) * H_];
        }
    }

#pragma unroll
    for (int cc = 0; cc < 16; cc++) {
        const int cur = cc % 3;
        if (cc < 14) {
            const int nb  = (cc + 2) % 3;
            const int off = (cc + 2) * 4;
#pragma unroll
            for (int q = 0; q < 4; q++) {
                wb[nb][q]     = pA[(off + q) * H_];
                wb[nb][4 + q] = pC[(off + q) * H_];
                wb[nb][8 + q] = pS[(off + q) * H_];
            }
        }
        const ull wa01 = pack2(wb[cur][0], wb[cur][1]);
        const ull wa23 = pack2(wb[cur][2], wb[cur][3]);
        const ull wc01 = pack2(wb[cur][4], wb[cur][5]);
        const ull wc23 = pack2(wb[cur][6], wb[cur][7]);
        const ull ws01 = pack2(wb[cur][8], wb[cur][9]);
        const ull ws23 = pack2(wb[cur][10], wb[cur][11]);
        const int d0 = dBase + cc * 4;
#pragma unroll
        for (int r = 0; r < RW; r++) {
            const ulonglong2 xv = *(const ulonglong2*)&xs[r][d0];
            fma2(accA[r], xv.x, wa01); fma2(accA[r], xv.y, wa23);
            fma2(accC[r], xv.x, wc01); fma2(accC[r], xv.y, wc23);
            fma2(accS[r], xv.x, ws01); fma2(accS[r], xv.y, ws23);
        }
    }

    if (half == 1) {
#pragma unroll
        for (int r = 0; r < RW; r++) {
            redA[r][h] = hadd2(accA[r]);
            redC[r][h] = hadd2(accC[r]);
            redS[r][h] = hadd2(accS[r]);
        }
    }
    __syncthreads();

    if (half == 0) {
        const float bc = b1c[h];
        const float bs = b1s[h];
        const float w2 = W2s[h];
#pragma unroll
        for (int r = 0; r < RW; r++) {
            const float a = hadd2(accA[r]) + redA[r][h];
            const float c = hadd2(accC[r]) + redC[r][h] + bc;
            gA[(size_t)(rowBase + r) * H_ + h] = a;
            gC[(size_t)(rowBase + r) * H_ + h] = c;
            float t = fmaxf(hadd2(accS[r]) + redS[r][h] + bs, 0.f) * w2;
#pragma unroll
            for (int off = 16; off > 0; off >>= 1)
                t += __shfl_down_sync(0xffffffffu, t, off);
            if ((h & 31) == 0) red4[h >> 5][r] = t;
        }
    }
    __syncthreads();
    if (tid < RW) {
        const float s = red4[0][tid] + red4[1][tid] + red4[2][tid] + red4[3][tid] + b2s[0];
        gDiag[rowBase + tid] = 1.f / (1.f + __expf(-s));
    }
}

// ---------------------------------------------------------------------------
// Pair kernel v8: 64x64 tile, 256 threads, 4x4 micro-tile (rows ty+16k, cols
// tx+16m), full h=128 per thread. Dynamic smem (~68KB), 1 block/SM, 8 warps
// with 16 independent FMA chains. St staged by aliasing onto As.
// ---------------------------------------------------------------------------
#define PSTRIDE 132
#define SMEM_PAIR_BYTES ((2 * 64 * PSTRIDE + 128 + 32) * 4)

__global__ __launch_bounds__(256) void pair_kernel(
    const float* __restrict__ W2c, const float* __restrict__ b2c,
    float* __restrict__ out)
{
    extern __shared__ float sm[];
    float* As = sm;                          // [64][132]
    float* Cs = sm + 64 * PSTRIDE;           // [64][132]
    float* ws = sm + 2 * 64 * PSTRIDE;       // [128]

    // triangular decode over 8x8 tile grid
    int t = blockIdx.x, ti = 0;
    while (t >= 8 - ti) { t -= 8 - ti; ti++; }
    const int tj = ti + t;
    const int b  = blockIdx.y;

    const int tid = threadIdx.x;
    const int i0 = ti * 64, j0 = tj * 64;

    // load 64 rows of gA / gC (float4, coalesced: 8 per thread each)
    {
        const float4* ga4 = (const float4*)(gA + ((size_t)b * N_ + i0) * H_);
        const float4* gc4 = (const float4*)(gC + ((size_t)b * N_ + j0) * H_);
#pragma unroll
        for (int k = 0; k < 8; k++) {
            const int e = k * 256 + tid;       // 0..2047
            const int r = e >> 5, c = e & 31;
            ((float4*)&As[r * PSTRIDE])[c] = ga4[r * 32 + c];
            ((float4*)&Cs[r * PSTRIDE])[c] = gc4[r * 32 + c];
        }
        if (tid < H_) ws[tid] = W2c[tid];
    }
    __syncthreads();

    const int ty = tid >> 4;     // 0..15 -> rows ty+16k
    const int tx = tid & 15;     // 0..15 -> cols tx+16m

    ull acc[4][4];
#pragma unroll
    for (int k = 0; k < 4; k++)
#pragma unroll
        for (int m = 0; m < 4; m++) acc[k][m] = 0ull;

#pragma unroll 2
    for (int hh = 0; hh < H_; hh += 4) {
        ulonglong2 av[4], cv[4];
#pragma unroll
        for (int k = 0; k < 4; k++)
            av[k] = *(const ulonglong2*)&As[(ty + 16 * k) * PSTRIDE + hh];
#pragma unroll
        for (int m = 0; m < 4; m++)
            cv[m] = *(const ulonglong2*)&Cs[(tx + 16 * m) * PSTRIDE + hh];
        const ulonglong2 wv = *(const ulonglong2*)&ws[hh];

#pragma unroll
        for (int k = 0; k < 4; k++) {
#pragma unroll
            for (int m = 0; m < 4; m++) {
                fma2(acc[k][m], relu2(add2(av[k].x, cv[m].x)), wv.x);
                fma2(acc[k][m], relu2(add2(av[k].y, cv[m].y)), wv.y);
            }
        }
    }

    const float bb = b2c[0];
    float sv[4][4];
#pragma unroll
    for (int k = 0; k < 4; k++)
#pragma unroll
        for (int m = 0; m < 4; m++)
            sv[k][m] = 1.f / (1.f + __expf(-(hadd2(acc[k][m]) + bb)));

    // stage results: alias St[64][65] onto As (all As/Cs reads done)
    __syncthreads();
    float* St = As;              // [64][65]
#define ST(i, j) St[(i) * 65 + (j)]

    if (ti != tj) {
#pragma unroll
        for (int k = 0; k < 4; k++)
#pragma unroll
            for (int m = 0; m < 4; m++)
                ST(ty + 16 * k, tx + 16 * m) = sv[k][m];
        __syncthreads();

        // normal block (i0, j0): coalesced float4
        for (int q = tid; q < 1024; q += 256) {
            const int r = q >> 4, c = (q & 15) * 4;
            float4 v = make_float4(ST(r, c), ST(r, c + 1), ST(r, c + 2), ST(r, c + 3));
            *(float4*)&out[((size_t)b * N_ + i0 + r) * N_ + j0 + c] = v;
        }
        // transposed block (j0, i0)
        for (int q = tid; q < 1024; q += 256) {
            const int r = q >> 4, c = (q & 15) * 4;
            float4 v = make_float4(ST(c, r), ST(c + 1, r), ST(c + 2, r), ST(c + 3, r));
            *(float4*)&out[((size_t)b * N_ + j0 + r) * N_ + i0 + c] = v;
        }
    } else {
        const int gi0 = b * N_ + i0;
#pragma unroll
        for (int k = 0; k < 4; k++) {
#pragma unroll
            for (int m = 0; m < 4; m++) {
                const int i = ty + 16 * k, j = tx + 16 * m;
                if (i < j)       { ST(i, j) = sv[k][m]; ST(j, i) = sv[k][m]; }
                else if (i == j) { ST(i, i) = gDiag[gi0 + i]; }
            }
        }
        __syncthreads();
        for (int q = tid; q < 1024; q += 256) {
            const int r = q >> 4, c = (q & 15) * 4;
            float4 v = make_float4(ST(r, c), ST(r, c + 1), ST(r, c + 2), ST(r, c + 3));
            *(float4*)&out[((size_t)b * N_ + i0 + r) * N_ + j0 + c] = v;
        }
    }
#undef ST
}

// ---------------------------------------------------------------------------
extern "C" void kernel_launch(void* const* d_in, const int* in_sizes, int n_in,
                              void* d_out, int out_size)
{
    const float* X   = (const float*)d_in[0];
    const float* W1c = (const float*)d_in[1];
    const float* b1c = (const float*)d_in[2];
    const float* W2c = (const float*)d_in[3];
    const float* b2c = (const float*)d_in[4];
    const float* W1s = (const float*)d_in[5];
    const float* b1s = (const float*)d_in[6];
    const float* W2s = (const float*)d_in[7];
    const float* b2s = (const float*)d_in[8];
    float* out = (float*)d_out;

    static bool attrSet = false;
    if (!attrSet) {
        cudaFuncSetAttribute(pair_kernel,
                             cudaFuncAttributeMaxDynamicSharedMemorySize,
                             SMEM_PAIR_BYTES);
        attrSet = true;
    }

    precompute_kernel<<<(B_ * N_) / RW, 256>>>(X, W1c, b1c, W1s, b1s, W2s, b2s);

    dim3 grid(36, B_);   // 8*9/2 triangular 64x64 tiles x batch
    pair_kernel<<<grid, 256, SMEM_PAIR_BYTES>>>(W2c, b2c, out);
}

// round 9
// speedup vs baseline: 1.7256x; 1.0919x over previous
#include <cuda_runtime.h>
#include <cuda_bf16.h>

#define B_ 4
#define N_ 512
#define D_ 128
#define H_ 128

typedef unsigned long long ull;

// ---- packed f32x2 helpers -------------------------------------------------
__device__ __forceinline__ void fma2(ull &a, ull x, ull w) {
    asm("fma.rn.f32x2 %0, %1, %2, %0;" : "+l"(a) : "l"(x), "l"(w));
}
__device__ __forceinline__ ull add2(ull a, ull b) {
    ull r; asm("add.rn.f32x2 %0, %1, %2;" : "=l"(r) : "l"(a), "l"(b)); return r;
}
__device__ __forceinline__ ull pack2(float lo, float hi) {
    ull r; asm("mov.b64 %0, {%1, %2};" : "=l"(r) : "f"(lo), "f"(hi)); return r;
}
__device__ __forceinline__ void unpack2(ull v, float &lo, float &hi) {
    asm("mov.b64 {%0, %1}, %2;" : "=f"(lo), "=f"(hi) : "l"(v));
}
__device__ __forceinline__ float hadd2(ull v) { float lo, hi; unpack2(v, lo, hi); return lo + hi; }
__device__ __forceinline__ ull relu2(ull v) {
    float lo, hi; unpack2(v, lo, hi);
    return pack2(fmaxf(lo, 0.f), fmaxf(hi, 0.f));
}

// ---- scratch --------------------------------------------------------------
__device__ float gA[B_ * N_ * H_];
__device__ float gC[B_ * N_ * H_];
__device__ float gDiag[B_ * N_];

// ---------------------------------------------------------------------------
// Precompute (round-4 version, measured ~7.9us): 8 rows/block, 256 threads =
// h(128) x d-half(2), grid 256. Distance-2 weight prefetch (3 buffers).
// ---------------------------------------------------------------------------
#define RW 8

__global__ __launch_bounds__(256) void precompute_kernel(
    const float* __restrict__ X,
    const float* __restrict__ W1c, const float* __restrict__ b1c,
    const float* __restrict__ W1s, const float* __restrict__ b1s,
    const float* __restrict__ W2s, const float* __restrict__ b2s)
{
    const int tid  = threadIdx.x;
    const int h    = tid & 127;
    const int half = tid >> 7;
    const int rowBase = blockIdx.x * RW;

    __shared__ float xs[RW][D_];
    __shared__ float redA[RW][H_];
    __shared__ float redC[RW][H_];
    __shared__ float redS[RW][H_];
    __shared__ float red4[4][RW];

    {
        const float4* src = (const float4*)(X + (size_t)rowBase * D_);
        float4* dst = (float4*)&xs[0][0];
        for (int t = tid; t < RW * D_ / 4; t += 256) dst[t] = src[t];
    }
    __syncthreads();

    ull accA[RW], accC[RW], accS[RW];
#pragma unroll
    for (int r = 0; r < RW; r++) { accA[r] = 0ull; accC[r] = 0ull; accS[r] = 0ull; }

    const int dBase = half * 64;
    const float* pA = W1c + (size_t)dBase * H_ + h;
    const float* pC = W1c + (size_t)(dBase + D_) * H_ + h;
    const float* pS = W1s + (size_t)dBase * H_ + h;

    float wb[3][12];
#pragma unroll
    for (int p = 0; p < 2; p++) {
#pragma unroll
        for (int q = 0; q < 4; q++) {
            wb[p][q]     = pA[(p * 4 + q) * H_];
            wb[p][4 + q] = pC[(p * 4 + q) * H_];
            wb[p][8 + q] = pS[(p * 4 + q) * H_];
        }
    }

#pragma unroll
    for (int cc = 0; cc < 16; cc++) {
        const int cur = cc % 3;
        if (cc < 14) {
            const int nb  = (cc + 2) % 3;
            const int off = (cc + 2) * 4;
#pragma unroll
            for (int q = 0; q < 4; q++) {
                wb[nb][q]     = pA[(off + q) * H_];
                wb[nb][4 + q] = pC[(off + q) * H_];
                wb[nb][8 + q] = pS[(off + q) * H_];
            }
        }
        const ull wa01 = pack2(wb[cur][0], wb[cur][1]);
        const ull wa23 = pack2(wb[cur][2], wb[cur][3]);
        const ull wc01 = pack2(wb[cur][4], wb[cur][5]);
        const ull wc23 = pack2(wb[cur][6], wb[cur][7]);
        const ull ws01 = pack2(wb[cur][8], wb[cur][9]);
        const ull ws23 = pack2(wb[cur][10], wb[cur][11]);
        const int d0 = dBase + cc * 4;
#pragma unroll
        for (int r = 0; r < RW; r++) {
            const ulonglong2 xv = *(const ulonglong2*)&xs[r][d0];
            fma2(accA[r], xv.x, wa01); fma2(accA[r], xv.y, wa23);
            fma2(accC[r], xv.x, wc01); fma2(accC[r], xv.y, wc23);
            fma2(accS[r], xv.x, ws01); fma2(accS[r], xv.y, ws23);
        }
    }

    if (half == 1) {
#pragma unroll
        for (int r = 0; r < RW; r++) {
            redA[r][h] = hadd2(accA[r]);
            redC[r][h] = hadd2(accC[r]);
            redS[r][h] = hadd2(accS[r]);
        }
    }
    __syncthreads();

    if (half == 0) {
        const float bc = b1c[h];
        const float bs = b1s[h];
        const float w2 = W2s[h];
#pragma unroll
        for (int r = 0; r < RW; r++) {
            const float a = hadd2(accA[r]) + redA[r][h];
            const float c = hadd2(accC[r]) + redC[r][h] + bc;
            gA[(size_t)(rowBase + r) * H_ + h] = a;
            gC[(size_t)(rowBase + r) * H_ + h] = c;
            float t = fmaxf(hadd2(accS[r]) + redS[r][h] + bs, 0.f) * w2;
#pragma unroll
            for (int off = 16; off > 0; off >>= 1)
                t += __shfl_down_sync(0xffffffffu, t, off);
            if ((h & 31) == 0) red4[h >> 5][r] = t;
        }
    }
    __syncthreads();
    if (tid < RW) {
        const float s = red4[0][tid] + red4[1][tid] + red4[2][tid] + red4[3][tid] + b2s[0];
        gDiag[rowBase + tid] = 1.f / (1.f + __expf(-s));
    }
}

// ---------------------------------------------------------------------------
// Pair kernel v9: 64x64 tile, 512 threads (16 warps), 4x2 micro-tile.
// ty = warp id -> A-row loads are pure warp broadcasts; tx = lane -> C loads
// conflict-free at 132-float stride. 16 warps/SM hides LDS+FMA latency.
// ---------------------------------------------------------------------------
#define PSTRIDE 132
#define SMEM_PAIR_BYTES ((2 * 64 * PSTRIDE + 128 + 32) * 4)

__global__ __launch_bounds__(512) void pair_kernel(
    const float* __restrict__ W2c, const float* __restrict__ b2c,
    float* __restrict__ out)
{
    extern __shared__ float sm[];
    float* As = sm;                          // [64][132]
    float* Cs = sm + 64 * PSTRIDE;           // [64][132]
    float* ws = sm + 2 * 64 * PSTRIDE;       // [128]

    // triangular decode over 8x8 tile grid
    int t = blockIdx.x, ti = 0;
    while (t >= 8 - ti) { t -= 8 - ti; ti++; }
    const int tj = ti + t;
    const int b  = blockIdx.y;

    const int tid = threadIdx.x;
    const int i0 = ti * 64, j0 = tj * 64;

    // load 64 rows of gA / gC (float4, coalesced: 4 per thread each)
    {
        const float4* ga4 = (const float4*)(gA + ((size_t)b * N_ + i0) * H_);
        const float4* gc4 = (const float4*)(gC + ((size_t)b * N_ + j0) * H_);
#pragma unroll
        for (int k = 0; k < 4; k++) {
            const int e = k * 512 + tid;       // 0..2047
            const int r = e >> 5, c = e & 31;
            ((float4*)&As[r * PSTRIDE])[c] = ga4[r * 32 + c];
            ((float4*)&Cs[r * PSTRIDE])[c] = gc4[r * 32 + c];
        }
        if (tid < H_) ws[tid] = W2c[tid];
    }
    __syncthreads();

    const int ty = tid >> 5;     // warp id 0..15 -> rows ty+16k (warp-uniform)
    const int tx = tid & 31;     // lane          -> cols tx+32m

    ull acc[4][2];
#pragma unroll
    for (int k = 0; k < 4; k++) { acc[k][0] = 0ull; acc[k][1] = 0ull; }

#pragma unroll 4
    for (int hh = 0; hh < H_; hh += 4) {
        ulonglong2 av[4], cv[2];
#pragma unroll
        for (int k = 0; k < 4; k++)
            av[k] = *(const ulonglong2*)&As[(ty + 16 * k) * PSTRIDE + hh];  // broadcast
#pragma unroll
        for (int m = 0; m < 2; m++)
            cv[m] = *(const ulonglong2*)&Cs[(tx + 32 * m) * PSTRIDE + hh];
        const ulonglong2 wv = *(const ulonglong2*)&ws[hh];

#pragma unroll
        for (int k = 0; k < 4; k++) {
#pragma unroll
            for (int m = 0; m < 2; m++) {
                fma2(acc[k][m], relu2(add2(av[k].x, cv[m].x)), wv.x);
                fma2(acc[k][m], relu2(add2(av[k].y, cv[m].y)), wv.y);
            }
        }
    }

    const float bb = b2c[0];
    float sv[4][2];
#pragma unroll
    for (int k = 0; k < 4; k++)
#pragma unroll
        for (int m = 0; m < 2; m++)
            sv[k][m] = 1.f / (1.f + __expf(-(hadd2(acc[k][m]) + bb)));

    // stage results: alias St[64][65] onto As (all As/Cs reads done)
    __syncthreads();
    float* St = As;
#define ST(i, j) St[(i) * 65 + (j)]

    if (ti != tj) {
#pragma unroll
        for (int k = 0; k < 4; k++)
#pragma unroll
            for (int m = 0; m < 2; m++)
                ST(ty + 16 * k, tx + 32 * m) = sv[k][m];
        __syncthreads();

        for (int q = tid; q < 1024; q += 512) {
            const int r = q >> 4, c = (q & 15) * 4;
            float4 v = make_float4(ST(r, c), ST(r, c + 1), ST(r, c + 2), ST(r, c + 3));
            *(float4*)&out[((size_t)b * N_ + i0 + r) * N_ + j0 + c] = v;
        }
        for (int q = tid; q < 1024; q += 512) {
            const int r = q >> 4, c = (q & 15) * 4;
            float4 v = make_float4(ST(c, r), ST(c + 1, r), ST(c + 2, r), ST(c + 3, r));
            *(float4*)&out[((size_t)b * N_ + j0 + r) * N_ + i0 + c] = v;
        }
    } else {
        const int gi0 = b * N_ + i0;
#pragma unroll
        for (int k = 0; k < 4; k++) {
#pragma unroll
            for (int m = 0; m < 2; m++) {
                const int i = ty + 16 * k, j = tx + 32 * m;
                if (i < j)       { ST(i, j) = sv[k][m]; ST(j, i) = sv[k][m]; }
                else if (i == j) { ST(i, i) = gDiag[gi0 + i]; }
            }
        }
        __syncthreads();
        for (int q = tid; q < 1024; q += 512) {
            const int r = q >> 4, c = (q & 15) * 4;
            float4 v = make_float4(ST(r, c), ST(r, c + 1), ST(r, c + 2), ST(r, c + 3));
            *(float4*)&out[((size_t)b * N_ + i0 + r) * N_ + j0 + c] = v;
        }
    }
#undef ST
}

// ---------------------------------------------------------------------------
extern "C" void kernel_launch(void* const* d_in, const int* in_sizes, int n_in,
                              void* d_out, int out_size)
{
    const float* X   = (const float*)d_in[0];
    const float* W1c = (const float*)d_in[1];
    const float* b1c = (const float*)d_in[2];
    const float* W2c = (const float*)d_in[3];
    const float* b2c = (const float*)d_in[4];
    const float* W1s = (const float*)d_in[5];
    const float* b1s = (const float*)d_in[6];
    const float* W2s = (const float*)d_in[7];
    const float* b2s = (const float*)d_in[8];
    float* out = (float*)d_out;

    static bool attrSet = false;
    if (!attrSet) {
        cudaFuncSetAttribute(pair_kernel,
                             cudaFuncAttributeMaxDynamicSharedMemorySize,
                             SMEM_PAIR_BYTES);
        attrSet = true;
    }

    precompute_kernel<<<(B_ * N_) / RW, 256>>>(X, W1c, b1c, W1s, b1s, W2s, b2s);

    dim3 grid(36, B_);   // 8*9/2 triangular 64x64 tiles x batch
    pair_kernel<<<grid, 512, SMEM_PAIR_BYTES>>>(W2c, b2c, out);
}